// round 7
// baseline (speedup 1.0000x reference)
#include <cuda_runtime.h>
#include <cstdint>
#include <cstddef>
#include <math.h>

// Problem dims
#define BATCH 64
#define EDIM 2048
#define HDIM 1024
#define SLEN 512
#define VOCAB 32000

#define SPLIT_T 8    // split-K for t1/t2 gemms
#define SPLIT_G 8    // split-K for g1/g2 gemms
#define SPLIT_O 2    // split-K for logits gemm
#define ATT_SPLIT 8  // split-S for attention

// ---------------- scratch (device globals; no allocation allowed) ----------------
__device__ float d_m   [BATCH * HDIM];
__device__ float d_hc  [BATCH * 2 * HDIM];
__device__ float d_P1  [SPLIT_T * BATCH * HDIM];
__device__ float d_P2  [SPLIT_T * BATCH * HDIM];
__device__ float d_P3  [SPLIT_G * BATCH * 4 * HDIM];
__device__ float d_P4  [SPLIT_G * BATCH * 4 * HDIM];
__device__ float d_PO  [SPLIT_O * BATCH * VOCAB];
__device__ float d_pctx[BATCH * ATT_SPLIT * HDIM];
__device__ float d_pms [BATCH * ATT_SPLIT * 2];

// ---------------- helpers ----------------
__device__ __forceinline__ void cp_async16(unsigned saddr, const void* gptr) {
    asm volatile("cp.async.cg.shared.global [%0], [%1], 16;" :: "r"(saddr), "l"(gptr));
}
#define CP_COMMIT() asm volatile("cp.async.commit_group;")

// pack two fp32 into bf16x2 hi parts + bf16x2 lo residuals (memory order: lo half = x)
__device__ __forceinline__ void split2(float x, float y, unsigned& hi, unsigned& lo) {
    asm("cvt.rn.bf16x2.f32 %0, %1, %2;" : "=r"(hi) : "f"(y), "f"(x));
    float hx = __uint_as_float(hi << 16);
    float hy = __uint_as_float(hi & 0xffff0000u);
    asm("cvt.rn.bf16x2.f32 %0, %1, %2;" : "=r"(lo) : "f"(y - hy), "f"(x - hx));
}

__device__ __forceinline__ void ldm_x4(unsigned* r, unsigned saddr) {
    asm volatile("ldmatrix.sync.aligned.m8n8.x4.shared.b16 {%0,%1,%2,%3}, [%4];"
                 : "=r"(r[0]), "=r"(r[1]), "=r"(r[2]), "=r"(r[3]) : "r"(saddr));
}
__device__ __forceinline__ void ldm_x4t(unsigned* r, unsigned saddr) {
    asm volatile("ldmatrix.sync.aligned.m8n8.x4.trans.shared.b16 {%0,%1,%2,%3}, [%4];"
                 : "=r"(r[0]), "=r"(r[1]), "=r"(r[2]), "=r"(r[3]) : "r"(saddr));
}

#define MMA_BF16(d, a, b0, b1) \
    asm volatile("mma.sync.aligned.m16n8k16.row.col.f32.bf16.bf16.f32 " \
        "{%0,%1,%2,%3}, {%4,%5,%6,%7}, {%8,%9}, {%0,%1,%2,%3};" \
        : "+f"(d[0]), "+f"(d[1]), "+f"(d[2]), "+f"(d[3]) \
        : "r"(a[0]), "r"(a[1]), "r"(a[2]), "r"(a[3]), "r"(b0), "r"(b1))

// Staging geometry (fp32, floats)
#define STAGES 3
#define AF_ST 36                 // 64 x 32 tile, row pad 36 (conflict-free LDS.128)
#define BF_ST 132                // 32 x 128 tile, row pad 132
#define AF_SZ (64 * AF_ST)       // 2304 floats
#define BF_SZ (32 * BF_ST)       // 4224 floats
#define STAGE_SZ (AF_SZ + BF_SZ) // 6528 floats
// bf16 geometry (halfs)
#define A_ST 40
#define B_ST 136
#define SMEM_BYTES (STAGES * STAGE_SZ * 4 + (64 * A_ST * 2 + 32 * B_ST * 2) * 2)  // 105984

// ---------------- bf16 3-term GEMM v3: C[64][N] = A @ W (+bias) ----------------
// A [64][K] row-major fp32, W [K][N] row-major fp32, N % 128 == 0, (K/gridDim.y) % 32 == 0.
// gridDim.y = split-K; if >1 writes partials at C + blockIdx.y*64*N (bias must be null).
// 3-stage cp.async fp32 staging -> convert to bf16 hi/lo smem -> ldmatrix + mma.
__global__ __launch_bounds__(256) void bf16gemm(
    const float* __restrict__ A, const float* __restrict__ W, int K,
    const float* __restrict__ bias, float* __restrict__ C, int N)
{
    extern __shared__ float sm[];
    float* stg = sm;  // [STAGES][STAGE_SZ]
    unsigned short* Ahi = (unsigned short*)(sm + STAGES * STAGE_SZ);
    unsigned short* Alo = Ahi + 64 * A_ST;
    unsigned short* Bhi = Alo + 64 * A_ST;
    unsigned short* Blo = Bhi + 32 * B_ST;

    const int tid  = threadIdx.x;
    const int lane = tid & 31;
    const int warp = tid >> 5;
    const int wm   = warp & 1;
    const int wn   = warp >> 1;
    const int qr   = lane >> 2;
    const int qc   = lane & 3;

    const int n0   = blockIdx.x * 128;
    const int Sy   = gridDim.y;
    const int Kc   = K / Sy;
    const int kbeg = blockIdx.y * Kc;
    const int nk   = Kc / 32;
    float* Cb = (Sy > 1) ? (C + (size_t)blockIdx.y * 64 * N) : C;

    const unsigned sStg = (unsigned)__cvta_generic_to_shared(stg);
    const unsigned sAh  = (unsigned)__cvta_generic_to_shared(Ahi);
    const unsigned sAl  = (unsigned)__cvta_generic_to_shared(Alo);
    const unsigned sBh  = (unsigned)__cvta_generic_to_shared(Bhi);
    const unsigned sBl  = (unsigned)__cvta_generic_to_shared(Blo);

    // cp.async coords (gmem-coalesced)
    const int aR = tid >> 2;          // 0..63
    const int aC = (tid & 3) * 8;     // 0,8,16,24
    const int bR = tid >> 3;          // 0..31
    const int bC = (tid & 7) * 16;    // 0..112
    // convert coords for B (transposed thread map, conflict-free LDS/STS)
    const int cR = tid & 31;          // row 0..31
    const int cG = (tid >> 5) * 16;   // col group

    float d[2][4][4];
#pragma unroll
    for (int i = 0; i < 2; i++)
#pragma unroll
        for (int j = 0; j < 4; j++)
#pragma unroll
            for (int q = 0; q < 4; q++) d[i][j][q] = 0.f;

    // --- issue one 32-k tile into stage s ---
    auto issue_tile = [&](int kt, int s) {
        const unsigned base = sStg + (unsigned)(s * STAGE_SZ * 4);
        const int k0 = kbeg + kt * 32;
        const float* ag = A + (size_t)aR * K + k0 + aC;
        unsigned da = base + (unsigned)((aR * AF_ST + aC) * 4);
        cp_async16(da, ag);
        cp_async16(da + 16, ag + 4);
        const float* bg = W + (size_t)(k0 + bR) * N + n0 + bC;
        unsigned db = base + (unsigned)((AF_SZ + bR * BF_ST + bC) * 4);
#pragma unroll
        for (int p = 0; p < 4; p++) cp_async16(db + p * 16, bg + p * 4);
    };

    // prologue: stages 0..STAGES-2
#pragma unroll
    for (int s = 0; s < STAGES - 1; s++) {
        if (s < nk) issue_tile(s, s);
        CP_COMMIT();
    }

    for (int t = 0; t < nk; t++) {
        // issue tile t+STAGES-1 (uniform commit keeps group counting constant)
        if (t + STAGES - 1 < nk) issue_tile(t + STAGES - 1, (t + STAGES - 1) % STAGES);
        CP_COMMIT();
        asm volatile("cp.async.wait_group %0;" :: "n"(STAGES - 1));
        __syncthreads();  // tile t visible to all; prev MMA done (bf16 reusable)

        // ---- convert stage t%STAGES -> bf16 hi/lo ----
        {
            const float* Sf = stg + (t % STAGES) * STAGE_SZ;
            // A: 8 floats per thread
            const float* ap = Sf + aR * AF_ST + aC;
            float4 a0 = *(const float4*)ap;
            float4 a1 = *(const float4*)(ap + 4);
            uint4 h, l;
            split2(a0.x, a0.y, h.x, l.x);
            split2(a0.z, a0.w, h.y, l.y);
            split2(a1.x, a1.y, h.z, l.z);
            split2(a1.z, a1.w, h.w, l.w);
            *(uint4*)&Ahi[aR * A_ST + aC] = h;
            *(uint4*)&Alo[aR * A_ST + aC] = l;
            // B: 16 floats per thread (transposed map)
            const float* bp = Sf + AF_SZ + cR * BF_ST + cG;
            float4 b0 = *(const float4*)bp;
            float4 b1 = *(const float4*)(bp + 4);
            float4 b2 = *(const float4*)(bp + 8);
            float4 b3 = *(const float4*)(bp + 12);
            split2(b0.x, b0.y, h.x, l.x);
            split2(b0.z, b0.w, h.y, l.y);
            split2(b1.x, b1.y, h.z, l.z);
            split2(b1.z, b1.w, h.w, l.w);
            *(uint4*)&Bhi[cR * B_ST + cG] = h;
            *(uint4*)&Blo[cR * B_ST + cG] = l;
            split2(b2.x, b2.y, h.x, l.x);
            split2(b2.z, b2.w, h.y, l.y);
            split2(b3.x, b3.y, h.z, l.z);
            split2(b3.z, b3.w, h.w, l.w);
            *(uint4*)&Bhi[cR * B_ST + cG + 8] = h;
            *(uint4*)&Blo[cR * B_ST + cG + 8] = l;
        }
        __syncthreads();

        // ---- MMA stage: 2 k-chunks of 16 ----
#pragma unroll
        for (int kc = 0; kc < 2; kc++) {
            const unsigned aoff =
                (unsigned)(((wm * 32 + (lane & 15)) * A_ST + kc * 16 + (lane >> 4) * 8) * 2);
            unsigned ah[2][4], al[2][4];
            ldm_x4(ah[0], sAh + aoff);
            ldm_x4(ah[1], sAh + aoff + 16 * A_ST * 2);
            ldm_x4(al[0], sAl + aoff);
            ldm_x4(al[1], sAl + aoff + 16 * A_ST * 2);

            const unsigned boff =
                (unsigned)(((kc * 16 + (lane & 15)) * B_ST + wn * 32 + (lane >> 4) * 8) * 2);
            unsigned bh[2][4], bl[2][4];
            ldm_x4t(bh[0], sBh + boff);
            ldm_x4t(bh[1], sBh + boff + 16 * 2);
            ldm_x4t(bl[0], sBl + boff);
            ldm_x4t(bl[1], sBl + boff + 16 * 2);

#pragma unroll
            for (int mi = 0; mi < 2; mi++)
#pragma unroll
                for (int ni = 0; ni < 4; ni++) {
                    const int p = ni >> 1, q = (ni & 1) * 2;
                    MMA_BF16(d[mi][ni], ah[mi], bh[p][q], bh[p][q + 1]);
                    MMA_BF16(d[mi][ni], al[mi], bh[p][q], bh[p][q + 1]);
                    MMA_BF16(d[mi][ni], ah[mi], bl[p][q], bl[p][q + 1]);
                }
        }
    }

    // epilogue
#pragma unroll
    for (int mi = 0; mi < 2; mi++) {
        const int r = wm * 32 + mi * 16 + qr;
#pragma unroll
        for (int ni = 0; ni < 4; ni++) {
            const int c = n0 + wn * 32 + ni * 8 + qc * 2;
            float2 v0 = make_float2(d[mi][ni][0], d[mi][ni][1]);
            float2 v1 = make_float2(d[mi][ni][2], d[mi][ni][3]);
            if (bias) {
                float2 bb = *(const float2*)(bias + c);
                v0.x += bb.x; v0.y += bb.y; v1.x += bb.x; v1.y += bb.y;
            }
            *(float2*)(Cb + (size_t)r * N + c)       = v0;
            *(float2*)(Cb + (size_t)(r + 8) * N + c) = v1;
        }
    }
}

// ---------------- m = (x@Wmx + bmx) * (h0@Wmh + bmh) ----------------
__global__ void m_kernel(const float* __restrict__ P1, const float* __restrict__ P2,
                         const float* __restrict__ bmx, const float* __restrict__ bmh,
                         float* __restrict__ m) {
    int idx = blockIdx.x * 256 + threadIdx.x;
    int j = idx & (HDIM - 1);
    float a = bmx[j], c = bmh[j];
#pragma unroll
    for (int s = 0; s < SPLIT_T; s++) {
        a += P1[(size_t)s * (BATCH * HDIM) + idx];
        c += P2[(size_t)s * (BATCH * HDIM) + idx];
    }
    m[idx] = a * c;
}

// ---------------- gates: reduce g partials, LSTM cell -> h into hc[:, :H] ----------------
__global__ void gates_kernel(const float* __restrict__ P3, const float* __restrict__ P4,
                             const float* __restrict__ bx, const float* __restrict__ bm,
                             const float* __restrict__ c0, float* __restrict__ hc) {
    int idx = blockIdx.x * 256 + threadIdx.x;
    int b = idx >> 10, j = idx & (HDIM - 1);
    float gv[4];
#pragma unroll
    for (int q = 0; q < 4; q++) {
        int colq = j + q * HDIM;
        float g = bx[colq] + bm[colq];
        size_t off = (size_t)b * (4 * HDIM) + colq;
#pragma unroll
        for (int s = 0; s < SPLIT_G; s++)
            g += P3[(size_t)s * (BATCH * 4 * HDIM) + off] + P4[(size_t)s * (BATCH * 4 * HDIM) + off];
        gv[q] = g;
    }
    float f  = 1.f / (1.f + expf(-gv[0]));
    float ii = 1.f / (1.f + expf(-gv[1]));
    float o  = 1.f / (1.f + expf(-gv[2]));
    float ct = tanhf(gv[3]);
    float c  = f * c0[idx] + ii * ct;
    hc[(size_t)b * (2 * HDIM) + j] = o * tanhf(c);
}

// ---------------- fused attention partial (flash-style online softmax) ----------------
__global__ __launch_bounds__(256) void attn_partial(
    const float* __restrict__ hc, const float* __restrict__ sv,
    float* __restrict__ pctx, float* __restrict__ pms)
{
    __shared__ float hs[HDIM];
    __shared__ float rows[8][HDIM];
    __shared__ float sscore[8];

    const int b   = blockIdx.x;
    const int sp  = blockIdx.y;
    const int tid = threadIdx.x;
    const int warp = tid >> 5, lane = tid & 31;

    ((float4*)hs)[tid] = ((const float4*)(hc + (size_t)b * 2 * HDIM))[tid];

    float4 ctx = make_float4(0.f, 0.f, 0.f, 0.f);
    float M = -INFINITY, S = 0.f;

    const float* svb = sv + ((size_t)b * SLEN + sp * (SLEN / ATT_SPLIT)) * HDIM;
    const int niter = (SLEN / ATT_SPLIT) / 8;

    for (int it = 0; it < niter; it++) {
        __syncthreads();
        const float4* src = (const float4*)(svb + (size_t)(it * 8 + warp) * HDIM);
        float acc = 0.f;
#pragma unroll
        for (int i = 0; i < 8; i++) {
            float4 v = src[lane + 32 * i];
            ((float4*)rows[warp])[lane + 32 * i] = v;
            float4 hv = ((const float4*)hs)[lane + 32 * i];
            acc += v.x * hv.x + v.y * hv.y + v.z * hv.z + v.w * hv.w;
        }
#pragma unroll
        for (int off = 16; off; off >>= 1) acc += __shfl_xor_sync(0xffffffffu, acc, off);
        if (lane == 0) sscore[warp] = acc;
        __syncthreads();

        float sc[8];
        float mx = M;
#pragma unroll
        for (int w = 0; w < 8; w++) { sc[w] = sscore[w]; mx = fmaxf(mx, sc[w]); }
        float scale = expf(M - mx);
        float e[8], esum = 0.f;
#pragma unroll
        for (int w = 0; w < 8; w++) { e[w] = expf(sc[w] - mx); esum += e[w]; }
        S = S * scale + esum;
        ctx.x *= scale; ctx.y *= scale; ctx.z *= scale; ctx.w *= scale;
#pragma unroll
        for (int w = 0; w < 8; w++) {
            float4 r = ((const float4*)rows[w])[tid];
            ctx.x += e[w] * r.x; ctx.y += e[w] * r.y;
            ctx.z += e[w] * r.z; ctx.w += e[w] * r.w;
        }
        M = mx;
    }

    ((float4*)(pctx + ((size_t)(b * ATT_SPLIT + sp)) * HDIM))[tid] = ctx;
    if (tid == 0) {
        pms[(b * ATT_SPLIT + sp) * 2]     = M;
        pms[(b * ATT_SPLIT + sp) * 2 + 1] = S;
    }
}

// ---------------- attention combine: ctx -> hc[:, H:2H] ----------------
__global__ void attn_combine(const float* __restrict__ pctx, const float* __restrict__ pms,
                             float* __restrict__ hc) {
    const int b = blockIdx.x, tid = threadIdx.x;
    float Mi[ATT_SPLIT], Si[ATT_SPLIT];
    float Mg = -INFINITY;
#pragma unroll
    for (int i = 0; i < ATT_SPLIT; i++) {
        Mi[i] = pms[(b * ATT_SPLIT + i) * 2];
        Si[i] = pms[(b * ATT_SPLIT + i) * 2 + 1];
        Mg = fmaxf(Mg, Mi[i]);
    }
    float wsum = 0.f, wi[ATT_SPLIT];
#pragma unroll
    for (int i = 0; i < ATT_SPLIT; i++) {
        wi[i] = expf(Mi[i] - Mg);
        wsum += wi[i] * Si[i];
    }
    float inv = 1.f / wsum;
    float4 c = make_float4(0.f, 0.f, 0.f, 0.f);
#pragma unroll
    for (int i = 0; i < ATT_SPLIT; i++) {
        float4 p = ((const float4*)(pctx + ((size_t)(b * ATT_SPLIT + i)) * HDIM))[tid];
        c.x += wi[i] * p.x; c.y += wi[i] * p.y;
        c.z += wi[i] * p.z; c.w += wi[i] * p.w;
    }
    c.x *= inv; c.y *= inv; c.z *= inv; c.w *= inv;
    ((float4*)(hc + (size_t)b * 2 * HDIM + HDIM))[tid] = c;
}

// ---------------- logits reduce: out = sum_s PO[s] + bias ----------------
__global__ void reduce_logits(const float* __restrict__ PO, const float* __restrict__ bout,
                              float* __restrict__ out) {
    int idx = blockIdx.x * 256 + threadIdx.x;
    int b = idx / VOCAB;
    int n = idx - b * VOCAB;
    float v = bout[n];
#pragma unroll
    for (int s = 0; s < SPLIT_O; s++)
        v += PO[(size_t)s * (BATCH * VOCAB) + idx];
    out[idx] = v;
}

// ---------------- launch ----------------
extern "C" void kernel_launch(void* const* d_in, const int* in_sizes, int n_in,
                              void* d_out, int out_size) {
    const float* x    = (const float*)d_in[0];
    const float* h0   = (const float*)d_in[1];
    const float* c0   = (const float*)d_in[2];
    const float* sv   = (const float*)d_in[3];
    const float* Wmx  = (const float*)d_in[4];
    const float* bmx  = (const float*)d_in[5];
    const float* Wmh  = (const float*)d_in[6];
    const float* bmh  = (const float*)d_in[7];
    const float* Wx   = (const float*)d_in[8];
    const float* bx   = (const float*)d_in[9];
    const float* Wm   = (const float*)d_in[10];
    const float* bm   = (const float*)d_in[11];
    const float* Wout = (const float*)d_in[12];
    const float* bout = (const float*)d_in[13];
    float* out = (float*)d_out;

    float *m, *hc, *P1, *P2, *P3, *P4, *PO, *pctx, *pms;
    cudaGetSymbolAddress((void**)&m,    d_m);
    cudaGetSymbolAddress((void**)&hc,   d_hc);
    cudaGetSymbolAddress((void**)&P1,   d_P1);
    cudaGetSymbolAddress((void**)&P2,   d_P2);
    cudaGetSymbolAddress((void**)&P3,   d_P3);
    cudaGetSymbolAddress((void**)&P4,   d_P4);
    cudaGetSymbolAddress((void**)&PO,   d_PO);
    cudaGetSymbolAddress((void**)&pctx, d_pctx);
    cudaGetSymbolAddress((void**)&pms,  d_pms);

    cudaFuncSetAttribute(bf16gemm, cudaFuncAttributeMaxDynamicSharedMemorySize, SMEM_BYTES);

    // t1 = x@Wmx, t2 = h0@Wmh  (split-K partials)
    bf16gemm<<<dim3(HDIM / 128, SPLIT_T), 256, SMEM_BYTES>>>(x,  Wmx, EDIM, nullptr, P1, HDIM);
    bf16gemm<<<dim3(HDIM / 128, SPLIT_T), 256, SMEM_BYTES>>>(h0, Wmh, HDIM, nullptr, P2, HDIM);
    m_kernel<<<(BATCH * HDIM) / 256, 256>>>(P1, P2, bmx, bmh, m);

    // g = x@Wx + m@Wm (+biases in gates kernel)
    bf16gemm<<<dim3(4 * HDIM / 128, SPLIT_G), 256, SMEM_BYTES>>>(x, Wx, EDIM, nullptr, P3, 4 * HDIM);
    bf16gemm<<<dim3(4 * HDIM / 128, SPLIT_G), 256, SMEM_BYTES>>>(m, Wm, HDIM, nullptr, P4, 4 * HDIM);
    gates_kernel<<<(BATCH * HDIM) / 256, 256>>>(P3, P4, bx, bm, c0, hc);

    // fused attention (single pass over sv)
    attn_partial<<<dim3(BATCH, ATT_SPLIT), 256>>>(hc, sv, pctx, pms);
    attn_combine<<<BATCH, 256>>>(pctx, pms, hc);

    // logits = [h|context] @ Wout + bout, split-K + reduce
    bf16gemm<<<dim3(VOCAB / 128, SPLIT_O), 256, SMEM_BYTES>>>(hc, Wout, 2 * HDIM, nullptr, PO, VOCAB);
    reduce_logits<<<(BATCH * VOCAB) / 256, 256>>>(PO, bout, out);
}